// round 7
// baseline (speedup 1.0000x reference)
#include <cuda_runtime.h>
#include <math.h>

#define NE_ 100000
#define NR_ 256
#define H_ 128
#define E_ 250000
#define NROWS_ (NE_ + NR_)

__device__ float g_h[(size_t)NROWS_ * H_];
__device__ float g_k[6][(size_t)NROWS_ * H_];
__device__ float g_q[(size_t)NE_ * H_];
__device__ float g_den[(size_t)NE_ * 8];

__device__ __forceinline__ unsigned long long pk2(float x, float y) {
    unsigned long long r; asm("mov.b64 %0,{%1,%2};" : "=l"(r) : "f"(x), "f"(y)); return r;
}
__device__ __forceinline__ void upk2(unsigned long long v, float& x, float& y) {
    asm("mov.b64 {%0,%1},%2;" : "=f"(x), "=f"(y) : "l"(v));
}
__device__ __forceinline__ void ffma2(unsigned long long& c, unsigned long long a, unsigned long long b) {
    asm("fma.rn.f32x2 %0,%1,%2,%0;" : "+l"(c) : "l"(a), "l"(b));
}
__device__ __forceinline__ float sigmoid_f(float x) { return 1.f / (1.f + expf(-x)); }
__device__ __forceinline__ float gelu_f(float x) { return 0.5f * x * (1.f + erff(x * 0.70710678118654752f)); }
__device__ __forceinline__ float softplus_f(float x) {
    return x > 0.f ? x + log1pf(expf(-x)) : log1pf(expf(x));
}

// C[64,NCOLS] = As[64,KDIM](stride lda) @ W[KDIM,NCOLS] row-major, epilogue applied.
// W is staged through shared memory Ws (KC rows x NCOLS) in chunks, loaded
// cooperatively once per block (removes per-warp duplicated global W loads).
// 256 threads: warp wy owns rows wy*8..wy*8+7; lane owns column pairs 2*(lane+32j).
template<int NCOLS, int KDIM, typename Epi>
__device__ __forceinline__ void gemmS(const float* As, int lda,
                                      const float* __restrict__ W,
                                      float* Ws,
                                      float* Cs, int ldc, Epi epi)
{
    constexpr int KC  = 32;
    constexpr int NP  = NCOLS / 64;
    const int lane = threadIdx.x & 31;
    const int wy   = threadIdx.x >> 5;
    unsigned long long acc[8][NP];
#pragma unroll
    for (int i = 0; i < 8; i++)
#pragma unroll
        for (int j = 0; j < NP; j++) acc[i][j] = 0ull;

    const float* a0 = As + (size_t)(wy * 8) * lda;

    for (int k0 = 0; k0 < KDIM; k0 += KC) {
        __syncthreads();
        // cooperative stage: KC*NCOLS floats
        const float4* Wg = reinterpret_cast<const float4*>(W + (size_t)k0 * NCOLS);
        float4* Wl = reinterpret_cast<float4*>(Ws);
        for (int t = threadIdx.x; t < KC * NCOLS / 4; t += 256) Wl[t] = Wg[t];
        __syncthreads();

#pragma unroll 4
        for (int kk = 0; kk < KC; kk++) {
            unsigned long long wv[NP];
#pragma unroll
            for (int j = 0; j < NP; j++)
                wv[j] = *reinterpret_cast<const unsigned long long*>(Ws + kk * NCOLS + 2 * (lane + 32 * j));
            const float* ak = a0 + (k0 + kk);
#pragma unroll
            for (int i = 0; i < 8; i++) {
                float hv = ak[(size_t)i * lda];
                unsigned long long hb = pk2(hv, hv);
#pragma unroll
                for (int j = 0; j < NP; j++) ffma2(acc[i][j], hb, wv[j]);
            }
        }
    }
    __syncthreads();
#pragma unroll
    for (int i = 0; i < 8; i++) {
        int row = wy * 8 + i;
#pragma unroll
        for (int j = 0; j < NP; j++) {
            float x, y; upk2(acc[i][j], x, y);
            int col = 2 * (lane + 32 * j);
            epi(row, col, x, y);
            Cs[(size_t)row * ldc + col]     = x;
            Cs[(size_t)row * ldc + col + 1] = y;
        }
    }
}

__global__ void STG_zero_kernel() {
    size_t i = ((size_t)blockIdx.x * 256 + threadIdx.x) * 4;
    const size_t nH = (size_t)NE_ * H_;
    if (i < nH) {
        *reinterpret_cast<float4*>(g_h + i) = make_float4(0.f, 0.f, 0.f, 0.f);
    } else {
        size_t j = i - nH;
        if (j < (size_t)NE_ * 8)
            *reinterpret_cast<float4*>(g_den + j) = make_float4(0.f, 0.f, 0.f, 0.f);
    }
}

__global__ __launch_bounds__(256) void STG_qall_kernel(
    const float* __restrict__ ent, const float* __restrict__ Wq, const float* __restrict__ bq)
{
    extern __shared__ float sm[];
    float* h_s = sm;                  // 64*128
    float* o_s = sm + 64 * 128;       // 64*128
    float* Ws  = o_s + 64 * 128;      // 32*128
    const int row0 = blockIdx.x * 64;
    for (int t = threadIdx.x; t < 64 * 32; t += 256) {
        int r = t >> 5, c = (t & 31) * 4; int g = row0 + r;
        float4 v = make_float4(0.f, 0.f, 0.f, 0.f);
        if (g < NE_) v = *reinterpret_cast<const float4*>(ent + (size_t)g * H_ + c);
        *reinterpret_cast<float4*>(h_s + r * H_ + c) = v;
    }
    gemmS<128, 128>(h_s, 128, Wq, Ws, o_s, 128,
        [&](int r, int c, float& x, float& y) { x += bq[c]; y += bq[c + 1]; });
    __syncthreads();
    for (int t = threadIdx.x; t < 64 * 32; t += 256) {
        int r = t >> 5, c = (t & 31) * 4; int g = row0 + r;
        if (g < NE_)
            *reinterpret_cast<float4*>(g_q + (size_t)g * H_ + c) =
                *reinterpret_cast<const float4*>(o_s + r * H_ + c);
    }
}

__global__ __launch_bounds__(256) void STG_edge_kernel(
    const float* __restrict__ ent, const float* __restrict__ drel,
    const float* __restrict__ Wk, const float* __restrict__ bk,
    const float* __restrict__ Wv, const float* __restrict__ bv,
    const float* __restrict__ wgW1, const float* __restrict__ wgb1,
    const float* __restrict__ wgW2, const float* __restrict__ wgb2,
    const float* __restrict__ time_coeff,
    const float* __restrict__ edge_time, const float* __restrict__ query_time,
    const int* __restrict__ src, const int* __restrict__ dst, const int* __restrict__ etyp)
{
    extern __shared__ float sm[];
    float* wi_s  = sm;                   // 64*256 : [src_e | rel_e*tm]
    float* hid_s = wi_s + 64 * 256;      // 64*128
    float* k_s   = hid_s + 64 * 128;     // 64*128
    float* v_s   = k_s + 64 * 128;       // 64*128
    float* tm_s  = v_s + 64 * 128;       // 64
    float* dw_s  = tm_s + 64;            // 64
    float* ex_s  = dw_s + 64;            // 64*8
    int*   dst_s = (int*)(ex_s + 64 * 8);
    int*   src_s = dst_s + 64;
    int*   et_s  = src_s + 64;
    int*   vld_s = et_s + 64;
    float* Ws    = (float*)(vld_s + 64); // 32*128

    const int tid = threadIdx.x;
    if (tid < 64) {
        int e = blockIdx.x * 64 + tid;
        int vld = (e < E_);
        int ee = vld ? e : 0;
        int s = src[ee], d = dst[ee], t = etyp[ee];
        float tc = fabsf(time_coeff[0]) + 1e-9f;
        float dte = (query_time[d] - edge_time[ee]) / tc;
        tm_s[tid] = sigmoid_f(dte);
        dst_s[tid] = d; src_s[tid] = s; et_s[tid] = t; vld_s[tid] = vld;
    }
    __syncthreads();

    for (int t = tid; t < 64 * 64; t += 256) {
        int r = t >> 6; int c = (t & 63) * 4;
        float4 v;
        if (c < 128) {
            v = *reinterpret_cast<const float4*>(ent + (size_t)src_s[r] * H_ + c);
        } else {
            float4 rv = *reinterpret_cast<const float4*>(drel + (size_t)et_s[r] * H_ + (c - 128));
            float tmv = tm_s[r];
            v.x = rv.x * tmv; v.y = rv.y * tmv; v.z = rv.z * tmv; v.w = rv.w * tmv;
        }
        *reinterpret_cast<float4*>(wi_s + r * 256 + c) = v;
    }

    // hidden = relu(wi @ wgW1[0:256] + tm*wgW1[256] + b1)   (wgW1 is [257,128])
    gemmS<128, 256>(wi_s, 256, wgW1, Ws, hid_s, 128,
        [&](int r, int c, float& x, float& y) {
            float tmv = tm_s[r];
            x = fmaxf(x + wgb1[c]     + tmv * wgW1[256 * 128 + c],     0.f);
            y = fmaxf(y + wgb1[c + 1] + tmv * wgW1[256 * 128 + c + 1], 0.f);
        });
    __syncthreads();

    {   // dw = sigmoid(hidden . wgW2 + b2), 4 threads/edge
        int r = tid >> 2, part = tid & 3;
        float s = 0.f;
#pragma unroll
        for (int j = 0; j < 32; j++) { int d = part * 32 + j; s += hid_s[r * 128 + d] * wgW2[d]; }
        s += __shfl_xor_sync(0xffffffffu, s, 1);
        s += __shfl_xor_sync(0xffffffffu, s, 2);
        if (part == 0) dw_s[r] = sigmoid_f(s + wgb2[0]);
    }
    __syncthreads();

    // msg = src_e * rel_e * dw  (in place over src half)
    for (int t = tid; t < 64 * 32; t += 256) {
        int r = t >> 5, c = (t & 31) * 4;
        float4 a = *reinterpret_cast<const float4*>(wi_s + r * 256 + c);
        float4 b = *reinterpret_cast<const float4*>(wi_s + r * 256 + 128 + c);
        float dw = dw_s[r];
        a.x *= b.x * dw; a.y *= b.y * dw; a.z *= b.z * dw; a.w *= b.w * dw;
        *reinterpret_cast<float4*>(wi_s + r * 256 + c) = a;
    }

    gemmS<128, 128>(wi_s, 256, Wk, Ws, k_s, 128,
        [&](int r, int c, float& x, float& y) { x += bk[c]; y += bk[c + 1]; });
    gemmS<128, 128>(wi_s, 256, Wv, Ws, v_s, 128,
        [&](int r, int c, float& x, float& y) { x += bv[c]; y += bv[c + 1]; });
    __syncthreads();

    {   // scores -> exp -> denominator (softmax shift skipped: exact invariance, |s| tiny here)
        int r = tid >> 2, part = tid & 3;
        int d = dst_s[r]; int vld = vld_s[r];
        const float* qrow = g_q + (size_t)d * H_;
        for (int u = 0; u < 2; u++) {
            int hh = part * 2 + u;
            float s = 0.f;
#pragma unroll
            for (int j = 0; j < 16; j += 4) {
                float4 qv = *reinterpret_cast<const float4*>(qrow + hh * 16 + j);
                float4 kv = *reinterpret_cast<const float4*>(k_s + r * 128 + hh * 16 + j);
                s += qv.x * kv.x + qv.y * kv.y + qv.z * kv.z + qv.w * kv.w;
            }
            float ex = expf(s * 0.25f);
            ex_s[r * 8 + hh] = ex;
            if (vld) atomicAdd(&g_den[(size_t)d * 8 + hh], ex);
        }
    }
    __syncthreads();

    {   // numerator scatter
        int r = tid >> 2, part = tid & 3;
        if (vld_s[r]) {
            int d = dst_s[r];
            float* xr = g_h + (size_t)d * H_;
#pragma unroll
            for (int j = 0; j < 32; j++) {
                int c = part * 32 + j;
                atomicAdd(&xr[c], ex_s[r * 8 + (c >> 4)] * v_s[r * 128 + c]);
            }
        }
    }
}

__global__ void STG_norm_kernel() {
    size_t i = (size_t)blockIdx.x * 256 + threadIdx.x;
    if (i >= (size_t)NE_ * H_) return;
    size_t n = i >> 7; int c = (int)(i & 127);
    float den = g_den[n * 8 + (c >> 4)];
    float x = g_h[i];
    g_h[i] = den > 0.f ? x / den : 0.f;
}

__global__ void STG_relcopy_kernel(const float* __restrict__ rel) {
    int i = blockIdx.x * 256 + threadIdx.x;
    if (i < NR_ * H_) g_h[(size_t)NE_ * H_ + i] = rel[i];
}

__global__ __launch_bounds__(256) void STG_feval_kernel(
    int nk, float c1, float c2, float c3, float c4, float c5, int kout_idx,
    const float* __restrict__ spW1, const float* __restrict__ spb1,
    const float* __restrict__ spW2, const float* __restrict__ spb2,
    const float* __restrict__ tmW1, const float* __restrict__ tmb1,
    const float* __restrict__ tmW2, const float* __restrict__ tmb2,
    const float* __restrict__ fgW,  const float* __restrict__ fgb)
{
    extern __shared__ float sm[];
    float* h_s   = sm;               // 64*128 (reused as sp)
    float* a1_s  = sm + 64 * 128;    // 64*256 (reused as tm)
    float* a2_s  = a1_s + 64 * 256;  // 64*64
    float* Ws    = a2_s + 64 * 64;   // 32*256
    float* sp_s  = h_s;
    float* tm2_s = a1_s;

    const int row0 = blockIdx.x * 64;
    for (int t = threadIdx.x; t < 64 * 32; t += 256) {
        int r = t >> 5, c = (t & 31) * 4; int g = row0 + r;
        float4 v = make_float4(0.f, 0.f, 0.f, 0.f);
        if (g < NROWS_) {
            size_t idx = (size_t)g * H_ + c;
            v = *reinterpret_cast<const float4*>(g_h + idx);
            float4 a;
            if (nk > 0) { a = *reinterpret_cast<const float4*>(g_k[0] + idx);
                v.x += c1 * a.x; v.y += c1 * a.y; v.z += c1 * a.z; v.w += c1 * a.w; }
            if (nk > 1) { a = *reinterpret_cast<const float4*>(g_k[1] + idx);
                v.x += c2 * a.x; v.y += c2 * a.y; v.z += c2 * a.z; v.w += c2 * a.w; }
            if (nk > 2) { a = *reinterpret_cast<const float4*>(g_k[2] + idx);
                v.x += c3 * a.x; v.y += c3 * a.y; v.z += c3 * a.z; v.w += c3 * a.w; }
            if (nk > 3) { a = *reinterpret_cast<const float4*>(g_k[3] + idx);
                v.x += c4 * a.x; v.y += c4 * a.y; v.z += c4 * a.z; v.w += c4 * a.w; }
            if (nk > 4) { a = *reinterpret_cast<const float4*>(g_k[4] + idx);
                v.x += c5 * a.x; v.y += c5 * a.y; v.z += c5 * a.z; v.w += c5 * a.w; }
        }
        *reinterpret_cast<float4*>(h_s + r * H_ + c) = v;
    }

    gemmS<256, 128>(h_s, 128, spW1, Ws, a1_s, 256,
        [&](int r, int c, float& x, float& y) { x = gelu_f(x + spb1[c]); y = gelu_f(y + spb1[c + 1]); });
    gemmS<64, 128>(h_s, 128, tmW1, Ws, a2_s, 64,
        [&](int r, int c, float& x, float& y) { x = softplus_f(x + tmb1[c]); y = softplus_f(y + tmb1[c + 1]); });
    __syncthreads();

    gemmS<128, 256>(a1_s, 256, spW2, Ws, sp_s, 128,
        [&](int r, int c, float& x, float& y) { x += spb2[c]; y += spb2[c + 1]; });
    __syncthreads();

    gemmS<128, 64>(a2_s, 64, tmW2, Ws, tm2_s, 128,
        [&](int r, int c, float& x, float& y) { x += tmb2[c]; y += tmb2[c + 1]; });
    __syncthreads();

    {   // gate + output: 4 threads/row, 32 cols each
        int r = threadIdx.x >> 2, part = threadIdx.x & 3;
        float s0 = 0.f, s1 = 0.f;
#pragma unroll
        for (int jj = 0; jj < 32; jj++) {
            int d = part * 32 + jj;
            float spv = sp_s[r * 128 + d], tmv = tm2_s[r * 128 + d];
            s0 += spv * fgW[2 * d]     + tmv * fgW[2 * (128 + d)];
            s1 += spv * fgW[2 * d + 1] + tmv * fgW[2 * (128 + d) + 1];
        }
        s0 += __shfl_xor_sync(0xffffffffu, s0, 1);
        s1 += __shfl_xor_sync(0xffffffffu, s1, 1);
        s0 += __shfl_xor_sync(0xffffffffu, s0, 2);
        s1 += __shfl_xor_sync(0xffffffffu, s1, 2);
        float g0 = sigmoid_f(s0 + fgb[0]);
        float g1 = sigmoid_f(s1 + fgb[1]);
        int g = row0 + r;
        if (g < NROWS_) {
            float* ko = g_k[kout_idx] + (size_t)g * H_;
#pragma unroll
            for (int jj = 0; jj < 32; jj += 4) {
                int d = part * 32 + jj;
                float4 o;
                o.x = g0 * sp_s[r * 128 + d + 0] + g1 * tm2_s[r * 128 + d + 0];
                o.y = g0 * sp_s[r * 128 + d + 1] + g1 * tm2_s[r * 128 + d + 1];
                o.z = g0 * sp_s[r * 128 + d + 2] + g1 * tm2_s[r * 128 + d + 2];
                o.w = g0 * sp_s[r * 128 + d + 3] + g1 * tm2_s[r * 128 + d + 3];
                *reinterpret_cast<float4*>(ko + d) = o;
            }
        }
    }
}

__global__ void STG_combine_kernel(float b1, float b3, float b4, float b5, float b6) {
    size_t i = ((size_t)blockIdx.x * 256 + threadIdx.x) * 4;
    if (i >= (size_t)NROWS_ * H_) return;
    float4 h = *reinterpret_cast<const float4*>(g_h + i);
    float4 a = *reinterpret_cast<const float4*>(g_k[0] + i);
    float4 c = *reinterpret_cast<const float4*>(g_k[2] + i);
    float4 d = *reinterpret_cast<const float4*>(g_k[3] + i);
    float4 e = *reinterpret_cast<const float4*>(g_k[4] + i);
    float4 f = *reinterpret_cast<const float4*>(g_k[5] + i);
    h.x += b1 * a.x + b3 * c.x + b4 * d.x + b5 * e.x + b6 * f.x;
    h.y += b1 * a.y + b3 * c.y + b4 * d.y + b5 * e.y + b6 * f.y;
    h.z += b1 * a.z + b3 * c.z + b4 * d.z + b5 * e.z + b6 * f.z;
    h.w += b1 * a.w + b3 * c.w + b4 * d.w + b5 * e.w + b6 * f.w;
    *reinterpret_cast<float4*>(g_h + i) = h;
}

__global__ void STG_outcopy_kernel(float* __restrict__ out, int n4) {
    int i = blockIdx.x * 256 + threadIdx.x;
    if (i < n4)
        *reinterpret_cast<float4*>(out + (size_t)i * 4) =
            *reinterpret_cast<const float4*>(g_h + (size_t)i * 4);
}

extern "C" void kernel_launch(void* const* d_in, const int* in_sizes, int n_in,
                              void* d_out, int out_size)
{
    (void)in_sizes; (void)n_in;
    const float* ent  = (const float*)d_in[0];
    const float* rel  = (const float*)d_in[1];
    const float* drel = (const float*)d_in[2];
    const float* Wq   = (const float*)d_in[3];
    const float* bq   = (const float*)d_in[4];
    const float* Wk   = (const float*)d_in[5];
    const float* bk   = (const float*)d_in[6];
    const float* Wv   = (const float*)d_in[7];
    const float* bv   = (const float*)d_in[8];
    const float* tcoef= (const float*)d_in[9];
    const float* wgW1 = (const float*)d_in[10];
    const float* wgb1 = (const float*)d_in[11];
    const float* wgW2 = (const float*)d_in[12];
    const float* wgb2 = (const float*)d_in[13];
    const float* spW1 = (const float*)d_in[14];
    const float* spb1 = (const float*)d_in[15];
    const float* spW2 = (const float*)d_in[16];
    const float* spb2 = (const float*)d_in[17];
    const float* tmW1 = (const float*)d_in[18];
    const float* tmb1 = (const float*)d_in[19];
    const float* tmW2 = (const float*)d_in[20];
    const float* tmb2 = (const float*)d_in[21];
    const float* fgW  = (const float*)d_in[22];
    const float* fgb  = (const float*)d_in[23];
    const float* edge_time  = (const float*)d_in[24];
    const float* query_time = (const float*)d_in[25];
    const int* src  = (const int*)d_in[26];
    const int* dst  = (const int*)d_in[27];
    const int* etyp = (const int*)d_in[28];
    float* out = (float*)d_out;

    const int SM_QALL = (2 * 64 * 128 + 32 * 128) * 4;                             // 81920
    const int SM_EDGE = (64*256 + 3*64*128 + 64 + 64 + 64*8 + 4*64 + 32*128) * 4;  // 183808
    const int SM_FEVL = (64*128 + 64*256 + 64*64 + 32*256) * 4;                    // 147456
    cudaFuncSetAttribute(STG_qall_kernel,  cudaFuncAttributeMaxDynamicSharedMemorySize, SM_QALL);
    cudaFuncSetAttribute(STG_edge_kernel,  cudaFuncAttributeMaxDynamicSharedMemorySize, SM_EDGE);
    cudaFuncSetAttribute(STG_feval_kernel, cudaFuncAttributeMaxDynamicSharedMemorySize, SM_FEVL);

    {
        size_t tot4 = ((size_t)NE_ * H_ + (size_t)NE_ * 8) / 4;
        int nb = (int)((tot4 + 255) / 256);
        STG_zero_kernel<<<nb, 256>>>();
    }
    STG_qall_kernel<<<(NE_ + 63) / 64, 256, SM_QALL>>>(ent, Wq, bq);
    STG_edge_kernel<<<(E_ + 63) / 64, 256, SM_EDGE>>>(
        ent, drel, Wk, bk, Wv, bv, wgW1, wgb1, wgW2, wgb2,
        tcoef, edge_time, query_time, src, dst, etyp);
    {
        size_t tot = (size_t)NE_ * H_;
        STG_norm_kernel<<<(int)((tot + 255) / 256), 256>>>();
    }
    STG_relcopy_kernel<<<(NR_ * H_ + 255) / 256, 256>>>(rel);

    const float dt = 1.0f / 8.0f;
    const int FB = (NROWS_ + 63) / 64;
    const int CB = (int)(((size_t)NROWS_ * H_ / 4 + 255) / 256);

    for (int s = 0; s < 8; s++) {
        STG_feval_kernel<<<FB, 256, SM_FEVL>>>(0, 0.f, 0.f, 0.f, 0.f, 0.f, 0,
            spW1, spb1, spW2, spb2, tmW1, tmb1, tmW2, tmb2, fgW, fgb);
        STG_feval_kernel<<<FB, 256, SM_FEVL>>>(1, dt * 0.2f, 0.f, 0.f, 0.f, 0.f, 1,
            spW1, spb1, spW2, spb2, tmW1, tmb1, tmW2, tmb2, fgW, fgb);
        STG_feval_kernel<<<FB, 256, SM_FEVL>>>(2,
            dt * (3.0f / 40.0f), dt * (9.0f / 40.0f), 0.f, 0.f, 0.f, 2,
            spW1, spb1, spW2, spb2, tmW1, tmb1, tmW2, tmb2, fgW, fgb);
        STG_feval_kernel<<<FB, 256, SM_FEVL>>>(3,
            dt * (44.0f / 45.0f), dt * (-56.0f / 15.0f), dt * (32.0f / 9.0f), 0.f, 0.f, 3,
            spW1, spb1, spW2, spb2, tmW1, tmb1, tmW2, tmb2, fgW, fgb);
        STG_feval_kernel<<<FB, 256, SM_FEVL>>>(4,
            dt * (19372.0f / 6561.0f), dt * (-25360.0f / 2187.0f),
            dt * (64448.0f / 6561.0f), dt * (-212.0f / 729.0f), 0.f, 4,
            spW1, spb1, spW2, spb2, tmW1, tmb1, tmW2, tmb2, fgW, fgb);
        STG_feval_kernel<<<FB, 256, SM_FEVL>>>(5,
            dt * (9017.0f / 3168.0f), dt * (-355.0f / 33.0f),
            dt * (46732.0f / 5247.0f), dt * (49.0f / 176.0f),
            dt * (-5103.0f / 18656.0f), 5,
            spW1, spb1, spW2, spb2, tmW1, tmb1, tmW2, tmb2, fgW, fgb);
        STG_combine_kernel<<<CB, 256>>>(
            dt * (35.0f / 384.0f), dt * (500.0f / 1113.0f), dt * (125.0f / 192.0f),
            dt * (-2187.0f / 6784.0f), dt * (11.0f / 84.0f));
    }

    {
        int n4 = out_size / 4;
        STG_outcopy_kernel<<<(n4 + 255) / 256, 256>>>(out, n4);
    }
}

// round 8
// speedup vs baseline: 1.3835x; 1.3835x over previous
#include <cuda_runtime.h>
#include <math.h>

#define NE_ 100000
#define NR_ 256
#define H_ 128
#define E_ 250000
#define NROWS_ (NE_ + NR_)

__device__ float g_h[(size_t)NROWS_ * H_];
__device__ float g_k[6][(size_t)NROWS_ * H_];
__device__ float g_q[(size_t)NE_ * H_];
__device__ float g_den[(size_t)NE_ * 8];

__device__ __forceinline__ unsigned long long pk2(float x, float y) {
    unsigned long long r; asm("mov.b64 %0,{%1,%2};" : "=l"(r) : "f"(x), "f"(y)); return r;
}
__device__ __forceinline__ void upk2(unsigned long long v, float& x, float& y) {
    asm("mov.b64 {%0,%1},%2;" : "=f"(x), "=f"(y) : "l"(v));
}
__device__ __forceinline__ void ffma2(unsigned long long& c, unsigned long long a, unsigned long long b) {
    asm("fma.rn.f32x2 %0,%1,%2,%0;" : "+l"(c) : "l"(a), "l"(b));
}
__device__ __forceinline__ float sigmoid_f(float x) { return 1.f / (1.f + expf(-x)); }
__device__ __forceinline__ float gelu_f(float x) { return 0.5f * x * (1.f + erff(x * 0.70710678118654752f)); }
__device__ __forceinline__ float softplus_f(float x) {
    return x > 0.f ? x + log1pf(expf(-x)) : log1pf(expf(x));
}

// C[TILE,NCOLS] = As[TILE,KDIM](stride lda) @ W[KDIM,NCOLS] row-major, epilogue applied.
// 256 threads / 8 warps: warp wy owns rows wy*RPW..; lane owns column pairs 2*(lane+32j).
// W is read directly from global (L1-cached; co-resident blocks share the stream).
template<int TILE, int NCOLS, int KDIM, typename Epi>
__device__ __forceinline__ void gemmR(const float* As, int lda,
                                      const float* __restrict__ W,
                                      float* Cs, int ldc, Epi epi)
{
    constexpr int NP  = NCOLS / 64;
    constexpr int RPW = TILE / 8;
    const int lane = threadIdx.x & 31;
    const int wy   = threadIdx.x >> 5;
    unsigned long long acc[RPW][NP];
#pragma unroll
    for (int i = 0; i < RPW; i++)
#pragma unroll
        for (int j = 0; j < NP; j++) acc[i][j] = 0ull;

    const float* a0 = As + (size_t)(wy * RPW) * lda;
#pragma unroll 4
    for (int k = 0; k < KDIM; k++) {
        unsigned long long wv[NP];
#pragma unroll
        for (int j = 0; j < NP; j++)
            wv[j] = *reinterpret_cast<const unsigned long long*>(W + (size_t)k * NCOLS + 2 * (lane + 32 * j));
#pragma unroll
        for (int i = 0; i < RPW; i++) {
            float hv = a0[(size_t)i * lda + k];
            unsigned long long hb = pk2(hv, hv);
#pragma unroll
            for (int j = 0; j < NP; j++) ffma2(acc[i][j], hb, wv[j]);
        }
    }
#pragma unroll
    for (int i = 0; i < RPW; i++) {
        int row = wy * RPW + i;
#pragma unroll
        for (int j = 0; j < NP; j++) {
            float x, y; upk2(acc[i][j], x, y);
            int col = 2 * (lane + 32 * j);
            epi(row, col, x, y);
            Cs[(size_t)row * ldc + col]     = x;
            Cs[(size_t)row * ldc + col + 1] = y;
        }
    }
}

__global__ void STG_zero_kernel() {
    size_t i = ((size_t)blockIdx.x * 256 + threadIdx.x) * 4;
    const size_t nH = (size_t)NE_ * H_;
    if (i < nH) {
        *reinterpret_cast<float4*>(g_h + i) = make_float4(0.f, 0.f, 0.f, 0.f);
    } else {
        size_t j = i - nH;
        if (j < (size_t)NE_ * 8)
            *reinterpret_cast<float4*>(g_den + j) = make_float4(0.f, 0.f, 0.f, 0.f);
    }
}

__global__ __launch_bounds__(256) void STG_qall_kernel(
    const float* __restrict__ ent, const float* __restrict__ Wq, const float* __restrict__ bq)
{
    extern __shared__ float sm[];
    float* h_s = sm;
    float* o_s = sm + 64 * 128;
    const int row0 = blockIdx.x * 64;
    for (int t = threadIdx.x; t < 64 * 32; t += 256) {
        int r = t >> 5, c = (t & 31) * 4; int g = row0 + r;
        float4 v = make_float4(0.f, 0.f, 0.f, 0.f);
        if (g < NE_) v = *reinterpret_cast<const float4*>(ent + (size_t)g * H_ + c);
        *reinterpret_cast<float4*>(h_s + r * H_ + c) = v;
    }
    __syncthreads();
    gemmR<64, 128, 128>(h_s, 128, Wq, o_s, 128,
        [&](int r, int c, float& x, float& y) { x += bq[c]; y += bq[c + 1]; });
    __syncthreads();
    for (int t = threadIdx.x; t < 64 * 32; t += 256) {
        int r = t >> 5, c = (t & 31) * 4; int g = row0 + r;
        if (g < NE_)
            *reinterpret_cast<float4*>(g_q + (size_t)g * H_ + c) =
                *reinterpret_cast<const float4*>(o_s + r * H_ + c);
    }
}

__global__ __launch_bounds__(256, 2) void STG_edge_kernel(
    const float* __restrict__ ent, const float* __restrict__ drel,
    const float* __restrict__ Wk, const float* __restrict__ bk,
    const float* __restrict__ Wv, const float* __restrict__ bv,
    const float* __restrict__ wgW1, const float* __restrict__ wgb1,
    const float* __restrict__ wgW2, const float* __restrict__ wgb2,
    const float* __restrict__ time_coeff,
    const float* __restrict__ edge_time, const float* __restrict__ query_time,
    const int* __restrict__ src, const int* __restrict__ dst, const int* __restrict__ etyp)
{
    extern __shared__ float sm[];
    float* wi_s  = sm;                   // 32*256 : [src_e | rel_e*tm]
    float* hid_s = wi_s + 32 * 256;      // 32*128
    float* k_s   = hid_s + 32 * 128;     // 32*128
    float* v_s   = k_s + 32 * 128;       // 32*128
    float* tm_s  = v_s + 32 * 128;       // 32
    float* dw_s  = tm_s + 32;            // 32
    float* ex_s  = dw_s + 32;            // 32*8
    int*   dst_s = (int*)(ex_s + 32 * 8);
    int*   src_s = dst_s + 32;
    int*   et_s  = src_s + 32;
    int*   vld_s = et_s + 32;

    const int tid = threadIdx.x;
    if (tid < 32) {
        int e = blockIdx.x * 32 + tid;
        int vld = (e < E_);
        int ee = vld ? e : 0;
        int s = src[ee], d = dst[ee], t = etyp[ee];
        float tc = fabsf(time_coeff[0]) + 1e-9f;
        float dte = (query_time[d] - edge_time[ee]) / tc;
        tm_s[tid] = sigmoid_f(dte);
        dst_s[tid] = d; src_s[tid] = s; et_s[tid] = t; vld_s[tid] = vld;
    }
    __syncthreads();

    for (int t = tid; t < 32 * 64; t += 256) {
        int r = t >> 6; int c = (t & 63) * 4;
        float4 v;
        if (c < 128) {
            v = *reinterpret_cast<const float4*>(ent + (size_t)src_s[r] * H_ + c);
        } else {
            float4 rv = *reinterpret_cast<const float4*>(drel + (size_t)et_s[r] * H_ + (c - 128));
            float tmv = tm_s[r];
            v.x = rv.x * tmv; v.y = rv.y * tmv; v.z = rv.z * tmv; v.w = rv.w * tmv;
        }
        *reinterpret_cast<float4*>(wi_s + r * 256 + c) = v;
    }
    __syncthreads();

    // hidden = relu(wi @ wgW1[0:256] + tm*wgW1[256] + b1)   (wgW1 is [257,128])
    gemmR<32, 128, 256>(wi_s, 256, wgW1, hid_s, 128,
        [&](int r, int c, float& x, float& y) {
            float tmv = tm_s[r];
            x = fmaxf(x + wgb1[c]     + tmv * wgW1[256 * 128 + c],     0.f);
            y = fmaxf(y + wgb1[c + 1] + tmv * wgW1[256 * 128 + c + 1], 0.f);
        });
    __syncthreads();

    {   // dw = sigmoid(hidden . wgW2 + b2), 8 threads/edge
        int r = tid >> 3, part = tid & 7;
        float s = 0.f;
#pragma unroll
        for (int j = 0; j < 16; j++) { int d = part * 16 + j; s += hid_s[r * 128 + d] * wgW2[d]; }
        s += __shfl_xor_sync(0xffffffffu, s, 1);
        s += __shfl_xor_sync(0xffffffffu, s, 2);
        s += __shfl_xor_sync(0xffffffffu, s, 4);
        if (part == 0) dw_s[r] = sigmoid_f(s + wgb2[0]);
    }
    __syncthreads();

    // msg = src_e * rel_e * dw  (in place over src half)
    for (int t = tid; t < 32 * 32; t += 256) {
        int r = t >> 5, c = (t & 31) * 4;
        float4 a = *reinterpret_cast<const float4*>(wi_s + r * 256 + c);
        float4 b = *reinterpret_cast<const float4*>(wi_s + r * 256 + 128 + c);
        float dw = dw_s[r];
        a.x *= b.x * dw; a.y *= b.y * dw; a.z *= b.z * dw; a.w *= b.w * dw;
        *reinterpret_cast<float4*>(wi_s + r * 256 + c) = a;
    }
    __syncthreads();

    gemmR<32, 128, 128>(wi_s, 256, Wk, k_s, 128,
        [&](int r, int c, float& x, float& y) { x += bk[c]; y += bk[c + 1]; });
    gemmR<32, 128, 128>(wi_s, 256, Wv, v_s, 128,
        [&](int r, int c, float& x, float& y) { x += bv[c]; y += bv[c + 1]; });
    __syncthreads();

    {   // scores -> exp -> denominator (softmax shift skipped: exact invariance, |s| tiny here)
        int r = tid >> 3, hh = tid & 7;
        int d = dst_s[r]; int vld = vld_s[r];
        const float* qrow = g_q + (size_t)d * H_;
        float s = 0.f;
#pragma unroll
        for (int j = 0; j < 16; j += 4) {
            float4 qv = *reinterpret_cast<const float4*>(qrow + hh * 16 + j);
            float4 kv = *reinterpret_cast<const float4*>(k_s + r * 128 + hh * 16 + j);
            s += qv.x * kv.x + qv.y * kv.y + qv.z * kv.z + qv.w * kv.w;
        }
        float ex = expf(s * 0.25f);
        ex_s[r * 8 + hh] = ex;
        if (vld) atomicAdd(&g_den[(size_t)d * 8 + hh], ex);
    }
    __syncthreads();

    {   // numerator scatter: 8 threads/edge, 16 cols each
        int r = tid >> 3, part = tid & 7;
        if (vld_s[r]) {
            int d = dst_s[r];
            float* xr = g_h + (size_t)d * H_;
            float exh0 = ex_s[r * 8 + part];
#pragma unroll
            for (int j = 0; j < 16; j++) {
                int c = part * 16 + j;
                atomicAdd(&xr[c], exh0 * v_s[r * 128 + c]);
            }
        }
    }
}

__global__ void STG_norm_kernel() {
    size_t i = (size_t)blockIdx.x * 256 + threadIdx.x;
    if (i >= (size_t)NE_ * H_) return;
    size_t n = i >> 7; int c = (int)(i & 127);
    float den = g_den[n * 8 + (c >> 4)];
    float x = g_h[i];
    g_h[i] = den > 0.f ? x / den : 0.f;
}

__global__ void STG_relcopy_kernel(const float* __restrict__ rel) {
    int i = blockIdx.x * 256 + threadIdx.x;
    if (i < NR_ * H_) g_h[(size_t)NE_ * H_ + i] = rel[i];
}

__global__ __launch_bounds__(256, 3) void STG_feval_kernel(
    int nk, float c1, float c2, float c3, float c4, float c5, int kout_idx,
    const float* __restrict__ spW1, const float* __restrict__ spb1,
    const float* __restrict__ spW2, const float* __restrict__ spb2,
    const float* __restrict__ tmW1, const float* __restrict__ tmb1,
    const float* __restrict__ tmW2, const float* __restrict__ tmb2,
    const float* __restrict__ fgW,  const float* __restrict__ fgb)
{
    extern __shared__ float sm[];
    float* h_s   = sm;               // 32*128 (reused as sp)
    float* a1_s  = sm + 32 * 128;    // 32*256 (reused as tm)
    float* a2_s  = a1_s + 32 * 256;  // 32*64
    float* sp_s  = h_s;
    float* tm2_s = a1_s;

    const int row0 = blockIdx.x * 32;
    for (int t = threadIdx.x; t < 32 * 32; t += 256) {
        int r = t >> 5, c = (t & 31) * 4; int g = row0 + r;
        float4 v = make_float4(0.f, 0.f, 0.f, 0.f);
        if (g < NROWS_) {
            size_t idx = (size_t)g * H_ + c;
            v = *reinterpret_cast<const float4*>(g_h + idx);
            float4 a;
            if (nk > 0) { a = *reinterpret_cast<const float4*>(g_k[0] + idx);
                v.x += c1 * a.x; v.y += c1 * a.y; v.z += c1 * a.z; v.w += c1 * a.w; }
            if (nk > 1) { a = *reinterpret_cast<const float4*>(g_k[1] + idx);
                v.x += c2 * a.x; v.y += c2 * a.y; v.z += c2 * a.z; v.w += c2 * a.w; }
            if (nk > 2) { a = *reinterpret_cast<const float4*>(g_k[2] + idx);
                v.x += c3 * a.x; v.y += c3 * a.y; v.z += c3 * a.z; v.w += c3 * a.w; }
            if (nk > 3) { a = *reinterpret_cast<const float4*>(g_k[3] + idx);
                v.x += c4 * a.x; v.y += c4 * a.y; v.z += c4 * a.z; v.w += c4 * a.w; }
            if (nk > 4) { a = *reinterpret_cast<const float4*>(g_k[4] + idx);
                v.x += c5 * a.x; v.y += c5 * a.y; v.z += c5 * a.z; v.w += c5 * a.w; }
        }
        *reinterpret_cast<float4*>(h_s + r * H_ + c) = v;
    }
    __syncthreads();

    gemmR<32, 256, 128>(h_s, 128, spW1, a1_s, 256,
        [&](int r, int c, float& x, float& y) { x = gelu_f(x + spb1[c]); y = gelu_f(y + spb1[c + 1]); });
    gemmR<32, 64, 128>(h_s, 128, tmW1, a2_s, 64,
        [&](int r, int c, float& x, float& y) { x = softplus_f(x + tmb1[c]); y = softplus_f(y + tmb1[c + 1]); });
    __syncthreads();

    gemmR<32, 128, 256>(a1_s, 256, spW2, sp_s, 128,
        [&](int r, int c, float& x, float& y) { x += spb2[c]; y += spb2[c + 1]; });
    __syncthreads();

    gemmR<32, 128, 64>(a2_s, 64, tmW2, tm2_s, 128,
        [&](int r, int c, float& x, float& y) { x += tmb2[c]; y += tmb2[c + 1]; });
    __syncthreads();

    {   // gate + output: 8 threads/row, 16 cols each
        int r = threadIdx.x >> 3, part = threadIdx.x & 7;
        float s0 = 0.f, s1 = 0.f;
#pragma unroll
        for (int jj = 0; jj < 16; jj++) {
            int d = part * 16 + jj;
            float spv = sp_s[r * 128 + d], tmv = tm2_s[r * 128 + d];
            s0 += spv * fgW[2 * d]     + tmv * fgW[2 * (128 + d)];
            s1 += spv * fgW[2 * d + 1] + tmv * fgW[2 * (128 + d) + 1];
        }
        s0 += __shfl_xor_sync(0xffffffffu, s0, 1);
        s1 += __shfl_xor_sync(0xffffffffu, s1, 1);
        s0 += __shfl_xor_sync(0xffffffffu, s0, 2);
        s1 += __shfl_xor_sync(0xffffffffu, s1, 2);
        s0 += __shfl_xor_sync(0xffffffffu, s0, 4);
        s1 += __shfl_xor_sync(0xffffffffu, s1, 4);
        float g0 = sigmoid_f(s0 + fgb[0]);
        float g1 = sigmoid_f(s1 + fgb[1]);
        int g = row0 + r;
        if (g < NROWS_) {
            float* ko = g_k[kout_idx] + (size_t)g * H_;
#pragma unroll
            for (int jj = 0; jj < 16; jj += 4) {
                int d = part * 16 + jj;
                float4 o;
                o.x = g0 * sp_s[r * 128 + d + 0] + g1 * tm2_s[r * 128 + d + 0];
                o.y = g0 * sp_s[r * 128 + d + 1] + g1 * tm2_s[r * 128 + d + 1];
                o.z = g0 * sp_s[r * 128 + d + 2] + g1 * tm2_s[r * 128 + d + 2];
                o.w = g0 * sp_s[r * 128 + d + 3] + g1 * tm2_s[r * 128 + d + 3];
                *reinterpret_cast<float4*>(ko + d) = o;
            }
        }
    }
}

__global__ void STG_combine_kernel(float b1, float b3, float b4, float b5, float b6) {
    size_t i = ((size_t)blockIdx.x * 256 + threadIdx.x) * 4;
    if (i >= (size_t)NROWS_ * H_) return;
    float4 h = *reinterpret_cast<const float4*>(g_h + i);
    float4 a = *reinterpret_cast<const float4*>(g_k[0] + i);
    float4 c = *reinterpret_cast<const float4*>(g_k[2] + i);
    float4 d = *reinterpret_cast<const float4*>(g_k[3] + i);
    float4 e = *reinterpret_cast<const float4*>(g_k[4] + i);
    float4 f = *reinterpret_cast<const float4*>(g_k[5] + i);
    h.x += b1 * a.x + b3 * c.x + b4 * d.x + b5 * e.x + b6 * f.x;
    h.y += b1 * a.y + b3 * c.y + b4 * d.y + b5 * e.y + b6 * f.y;
    h.z += b1 * a.z + b3 * c.z + b4 * d.z + b5 * e.z + b6 * f.z;
    h.w += b1 * a.w + b3 * c.w + b4 * d.w + b5 * e.w + b6 * f.w;
    *reinterpret_cast<float4*>(g_h + i) = h;
}

__global__ void STG_outcopy_kernel(float* __restrict__ out, int n4) {
    int i = blockIdx.x * 256 + threadIdx.x;
    if (i < n4)
        *reinterpret_cast<float4*>(out + (size_t)i * 4) =
            *reinterpret_cast<const float4*>(g_h + (size_t)i * 4);
}

extern "C" void kernel_launch(void* const* d_in, const int* in_sizes, int n_in,
                              void* d_out, int out_size)
{
    (void)in_sizes; (void)n_in;
    const float* ent  = (const float*)d_in[0];
    const float* rel  = (const float*)d_in[1];
    const float* drel = (const float*)d_in[2];
    const float* Wq   = (const float*)d_in[3];
    const float* bq   = (const float*)d_in[4];
    const float* Wk   = (const float*)d_in[5];
    const float* bk   = (const float*)d_in[6];
    const float* Wv   = (const float*)d_in[7];
    const float* bv   = (const float*)d_in[8];
    const float* tcoef= (const float*)d_in[9];
    const float* wgW1 = (const float*)d_in[10];
    const float* wgb1 = (const float*)d_in[11];
    const float* wgW2 = (const float*)d_in[12];
    const float* wgb2 = (const float*)d_in[13];
    const float* spW1 = (const float*)d_in[14];
    const float* spb1 = (const float*)d_in[15];
    const float* spW2 = (const float*)d_in[16];
    const float* spb2 = (const float*)d_in[17];
    const float* tmW1 = (const float*)d_in[18];
    const float* tmb1 = (const float*)d_in[19];
    const float* tmW2 = (const float*)d_in[20];
    const float* tmb2 = (const float*)d_in[21];
    const float* fgW  = (const float*)d_in[22];
    const float* fgb  = (const float*)d_in[23];
    const float* edge_time  = (const float*)d_in[24];
    const float* query_time = (const float*)d_in[25];
    const int* src  = (const int*)d_in[26];
    const int* dst  = (const int*)d_in[27];
    const int* etyp = (const int*)d_in[28];
    float* out = (float*)d_out;

    const int SM_QALL = 2 * 64 * 128 * 4;                                   // 65536
    const int SM_EDGE = (32*256 + 3*32*128 + 32 + 32 + 32*8 + 4*32) * 4;    // 83712
    const int SM_FEVL = (32*128 + 32*256 + 32*64) * 4;                      // 57344
    cudaFuncSetAttribute(STG_qall_kernel,  cudaFuncAttributeMaxDynamicSharedMemorySize, SM_QALL);
    cudaFuncSetAttribute(STG_edge_kernel,  cudaFuncAttributeMaxDynamicSharedMemorySize, SM_EDGE);
    cudaFuncSetAttribute(STG_feval_kernel, cudaFuncAttributeMaxDynamicSharedMemorySize, SM_FEVL);

    {
        size_t tot4 = ((size_t)NE_ * H_ + (size_t)NE_ * 8) / 4;
        int nb = (int)((tot4 + 255) / 256);
        STG_zero_kernel<<<nb, 256>>>();
    }
    STG_qall_kernel<<<(NE_ + 63) / 64, 256, SM_QALL>>>(ent, Wq, bq);
    STG_edge_kernel<<<(E_ + 31) / 32, 256, SM_EDGE>>>(
        ent, drel, Wk, bk, Wv, bv, wgW1, wgb1, wgW2, wgb2,
        tcoef, edge_time, query_time, src, dst, etyp);
    {
        size_t tot = (size_t)NE_ * H_;
        STG_norm_kernel<<<(int)((tot + 255) / 256), 256>>>();
    }
    STG_relcopy_kernel<<<(NR_ * H_ + 255) / 256, 256>>>(rel);

    const float dt = 1.0f / 8.0f;
    const int FB = (NROWS_ + 31) / 32;
    const int CB = (int)(((size_t)NROWS_ * H_ / 4 + 255) / 256);

    for (int s = 0; s < 8; s++) {
        STG_feval_kernel<<<FB, 256, SM_FEVL>>>(0, 0.f, 0.f, 0.f, 0.f, 0.f, 0,
            spW1, spb1, spW2, spb2, tmW1, tmb1, tmW2, tmb2, fgW, fgb);
        STG_feval_kernel<<<FB, 256, SM_FEVL>>>(1, dt * 0.2f, 0.f, 0.f, 0.f, 0.f, 1,
            spW1, spb1, spW2, spb2, tmW1, tmb1, tmW2, tmb2, fgW, fgb);
        STG_feval_kernel<<<FB, 256, SM_FEVL>>>(2,
            dt * (3.0f / 40.0f), dt * (9.0f / 40.0f), 0.f, 0.f, 0.f, 2,
            spW1, spb1, spW2, spb2, tmW1, tmb1, tmW2, tmb2, fgW, fgb);
        STG_feval_kernel<<<FB, 256, SM_FEVL>>>(3,
            dt * (44.0f / 45.0f), dt * (-56.0f / 15.0f), dt * (32.0f / 9.0f), 0.f, 0.f, 3,
            spW1, spb1, spW2, spb2, tmW1, tmb1, tmW2, tmb2, fgW, fgb);
        STG_feval_kernel<<<FB, 256, SM_FEVL>>>(4,
            dt * (19372.0f / 6561.0f), dt * (-25360.0f / 2187.0f),
            dt * (64448.0f / 6561.0f), dt * (-212.0f / 729.0f), 0.f, 4,
            spW1, spb1, spW2, spb2, tmW1, tmb1, tmW2, tmb2, fgW, fgb);
        STG_feval_kernel<<<FB, 256, SM_FEVL>>>(5,
            dt * (9017.0f / 3168.0f), dt * (-355.0f / 33.0f),
            dt * (46732.0f / 5247.0f), dt * (49.0f / 176.0f),
            dt * (-5103.0f / 18656.0f), 5,
            spW1, spb1, spW2, spb2, tmW1, tmb1, tmW2, tmb2, fgW, fgb);
        STG_combine_kernel<<<CB, 256>>>(
            dt * (35.0f / 384.0f), dt * (500.0f / 1113.0f), dt * (125.0f / 192.0f),
            dt * (-2187.0f / 6784.0f), dt * (11.0f / 84.0f));
    }

    {
        int n4 = out_size / 4;
        STG_outcopy_kernel<<<(n4 + 255) / 256, 256>>>(out, n4);
    }
}

// round 9
// speedup vs baseline: 1.4931x; 1.0792x over previous
#include <cuda_runtime.h>
#include <math.h>

#define NE_ 100000
#define NR_ 256
#define H_ 128
#define E_ 250000
#define NROWS_ (NE_ + NR_)

__device__ float g_h[(size_t)NROWS_ * H_];
__device__ float g_k[6][(size_t)NROWS_ * H_];
__device__ float g_q[(size_t)NE_ * H_];
__device__ float g_den[(size_t)NE_ * 8];

__device__ __forceinline__ unsigned long long pk2(float x, float y) {
    unsigned long long r; asm("mov.b64 %0,{%1,%2};" : "=l"(r) : "f"(x), "f"(y)); return r;
}
__device__ __forceinline__ void upk2(unsigned long long v, float& x, float& y) {
    asm("mov.b64 {%0,%1},%2;" : "=f"(x), "=f"(y) : "l"(v));
}
__device__ __forceinline__ void ffma2(unsigned long long& c, unsigned long long a, unsigned long long b) {
    asm("fma.rn.f32x2 %0,%1,%2,%0;" : "+l"(c) : "l"(a), "l"(b));
}
__device__ __forceinline__ float sigmoid_f(float x) { return 1.f / (1.f + expf(-x)); }
__device__ __forceinline__ float gelu_f(float x) { return 0.5f * x * (1.f + erff(x * 0.70710678118654752f)); }
__device__ __forceinline__ float softplus_f(float x) {
    return x > 0.f ? x + log1pf(expf(-x)) : log1pf(expf(x));
}

// C[TILE,NCOLS] = As[TILE,KDIM](stride lda) @ W[KDIM,NCOLS] row-major, epilogue applied.
// 256 threads / 8 warps partitioned as WCOL=NCOLS/64 column stripes x WROW=8/WCOL
// row groups. Each lane owns ONE column pair -> warps load DISJOINT W columns
// (duplication factor WROW instead of 8). A is read as LDS.128 broadcasts per
// 4-k group.
template<int TILE, int NCOLS, int KDIM, typename Epi>
__device__ __forceinline__ void gemmC(const float* As, int lda,
                                      const float* __restrict__ W,
                                      float* Cs, int ldc, Epi epi)
{
    constexpr int WCOL = (NCOLS / 64) < 8 ? (NCOLS / 64) : 8;
    constexpr int WROW = 8 / WCOL;
    constexpr int ROWS = TILE / WROW;
    const int lane = threadIdx.x & 31;
    const int w    = threadIdx.x >> 5;
    const int wc   = w % WCOL;
    const int wr   = w / WCOL;
    unsigned long long acc[ROWS];
#pragma unroll
    for (int i = 0; i < ROWS; i++) acc[i] = 0ull;

    const float* a0 = As + (size_t)(wr * ROWS) * lda;
    const float* Wp = W + 2 * lane + 64 * wc;

#pragma unroll 2
    for (int k0 = 0; k0 < KDIM; k0 += 4) {
        unsigned long long wv0 = *reinterpret_cast<const unsigned long long*>(Wp + (size_t)(k0 + 0) * NCOLS);
        unsigned long long wv1 = *reinterpret_cast<const unsigned long long*>(Wp + (size_t)(k0 + 1) * NCOLS);
        unsigned long long wv2 = *reinterpret_cast<const unsigned long long*>(Wp + (size_t)(k0 + 2) * NCOLS);
        unsigned long long wv3 = *reinterpret_cast<const unsigned long long*>(Wp + (size_t)(k0 + 3) * NCOLS);
#pragma unroll
        for (int i = 0; i < ROWS; i++) {
            float4 av = *reinterpret_cast<const float4*>(a0 + (size_t)i * lda + k0);
            ffma2(acc[i], pk2(av.x, av.x), wv0);
            ffma2(acc[i], pk2(av.y, av.y), wv1);
            ffma2(acc[i], pk2(av.z, av.z), wv2);
            ffma2(acc[i], pk2(av.w, av.w), wv3);
        }
    }
#pragma unroll
    for (int i = 0; i < ROWS; i++) {
        int row = wr * ROWS + i;
        float x, y; upk2(acc[i], x, y);
        int col = 2 * lane + 64 * wc;
        epi(row, col, x, y);
        Cs[(size_t)row * ldc + col]     = x;
        Cs[(size_t)row * ldc + col + 1] = y;
    }
}

__global__ void STG_zero_kernel() {
    size_t i = ((size_t)blockIdx.x * 256 + threadIdx.x) * 4;
    const size_t nH = (size_t)NE_ * H_;
    if (i < nH) {
        *reinterpret_cast<float4*>(g_h + i) = make_float4(0.f, 0.f, 0.f, 0.f);
    } else {
        size_t j = i - nH;
        if (j < (size_t)NE_ * 8)
            *reinterpret_cast<float4*>(g_den + j) = make_float4(0.f, 0.f, 0.f, 0.f);
    }
}

__global__ __launch_bounds__(256) void STG_qall_kernel(
    const float* __restrict__ ent, const float* __restrict__ Wq, const float* __restrict__ bq)
{
    extern __shared__ float sm[];
    float* h_s = sm;
    float* o_s = sm + 64 * 128;
    const int row0 = blockIdx.x * 64;
    for (int t = threadIdx.x; t < 64 * 32; t += 256) {
        int r = t >> 5, c = (t & 31) * 4; int g = row0 + r;
        float4 v = make_float4(0.f, 0.f, 0.f, 0.f);
        if (g < NE_) v = *reinterpret_cast<const float4*>(ent + (size_t)g * H_ + c);
        *reinterpret_cast<float4*>(h_s + r * H_ + c) = v;
    }
    __syncthreads();
    gemmC<64, 128, 128>(h_s, 128, Wq, o_s, 128,
        [&](int r, int c, float& x, float& y) { x += bq[c]; y += bq[c + 1]; });
    __syncthreads();
    for (int t = threadIdx.x; t < 64 * 32; t += 256) {
        int r = t >> 5, c = (t & 31) * 4; int g = row0 + r;
        if (g < NE_)
            *reinterpret_cast<float4*>(g_q + (size_t)g * H_ + c) =
                *reinterpret_cast<const float4*>(o_s + r * H_ + c);
    }
}

__global__ __launch_bounds__(256, 2) void STG_edge_kernel(
    const float* __restrict__ ent, const float* __restrict__ drel,
    const float* __restrict__ Wk, const float* __restrict__ bk,
    const float* __restrict__ Wv, const float* __restrict__ bv,
    const float* __restrict__ wgW1, const float* __restrict__ wgb1,
    const float* __restrict__ wgW2, const float* __restrict__ wgb2,
    const float* __restrict__ time_coeff,
    const float* __restrict__ edge_time, const float* __restrict__ query_time,
    const int* __restrict__ src, const int* __restrict__ dst, const int* __restrict__ etyp)
{
    extern __shared__ float sm[];
    float* wi_s  = sm;                   // 32*256 : [src_e | rel_e*tm]
    float* hid_s = wi_s + 32 * 256;      // 32*128
    float* k_s   = hid_s + 32 * 128;     // 32*128
    float* v_s   = k_s + 32 * 128;       // 32*128
    float* tm_s  = v_s + 32 * 128;       // 32
    float* dw_s  = tm_s + 32;            // 32
    float* ex_s  = dw_s + 32;            // 32*8
    int*   dst_s = (int*)(ex_s + 32 * 8);
    int*   src_s = dst_s + 32;
    int*   et_s  = src_s + 32;
    int*   vld_s = et_s + 32;

    const int tid = threadIdx.x;
    if (tid < 32) {
        int e = blockIdx.x * 32 + tid;
        int vld = (e < E_);
        int ee = vld ? e : 0;
        int s = src[ee], d = dst[ee], t = etyp[ee];
        float tc = fabsf(time_coeff[0]) + 1e-9f;
        float dte = (query_time[d] - edge_time[ee]) / tc;
        tm_s[tid] = sigmoid_f(dte);
        dst_s[tid] = d; src_s[tid] = s; et_s[tid] = t; vld_s[tid] = vld;
    }
    __syncthreads();

    for (int t = tid; t < 32 * 64; t += 256) {
        int r = t >> 6; int c = (t & 63) * 4;
        float4 v;
        if (c < 128) {
            v = *reinterpret_cast<const float4*>(ent + (size_t)src_s[r] * H_ + c);
        } else {
            float4 rv = *reinterpret_cast<const float4*>(drel + (size_t)et_s[r] * H_ + (c - 128));
            float tmv = tm_s[r];
            v.x = rv.x * tmv; v.y = rv.y * tmv; v.z = rv.z * tmv; v.w = rv.w * tmv;
        }
        *reinterpret_cast<float4*>(wi_s + r * 256 + c) = v;
    }
    __syncthreads();

    // hidden = relu(wi @ wgW1[0:256] + tm*wgW1[256] + b1)   (wgW1 is [257,128])
    gemmC<32, 128, 256>(wi_s, 256, wgW1, hid_s, 128,
        [&](int r, int c, float& x, float& y) {
            float tmv = tm_s[r];
            x = fmaxf(x + wgb1[c]     + tmv * wgW1[256 * 128 + c],     0.f);
            y = fmaxf(y + wgb1[c + 1] + tmv * wgW1[256 * 128 + c + 1], 0.f);
        });
    __syncthreads();

    {   // dw = sigmoid(hidden . wgW2 + b2), 8 threads/edge
        int r = tid >> 3, part = tid & 7;
        float s = 0.f;
#pragma unroll
        for (int j = 0; j < 16; j++) { int d = part * 16 + j; s += hid_s[r * 128 + d] * wgW2[d]; }
        s += __shfl_xor_sync(0xffffffffu, s, 1);
        s += __shfl_xor_sync(0xffffffffu, s, 2);
        s += __shfl_xor_sync(0xffffffffu, s, 4);
        if (part == 0) dw_s[r] = sigmoid_f(s + wgb2[0]);
    }
    __syncthreads();

    // msg = src_e * rel_e * dw  (in place over src half)
    for (int t = tid; t < 32 * 32; t += 256) {
        int r = t >> 5, c = (t & 31) * 4;
        float4 a = *reinterpret_cast<const float4*>(wi_s + r * 256 + c);
        float4 b = *reinterpret_cast<const float4*>(wi_s + r * 256 + 128 + c);
        float dw = dw_s[r];
        a.x *= b.x * dw; a.y *= b.y * dw; a.z *= b.z * dw; a.w *= b.w * dw;
        *reinterpret_cast<float4*>(wi_s + r * 256 + c) = a;
    }
    __syncthreads();

    gemmC<32, 128, 128>(wi_s, 256, Wk, k_s, 128,
        [&](int r, int c, float& x, float& y) { x += bk[c]; y += bk[c + 1]; });
    gemmC<32, 128, 128>(wi_s, 256, Wv, v_s, 128,
        [&](int r, int c, float& x, float& y) { x += bv[c]; y += bv[c + 1]; });
    __syncthreads();

    {   // scores -> exp -> denominator (softmax shift skipped: exact invariance, |s| tiny here)
        int r = tid >> 3, hh = tid & 7;
        int d = dst_s[r]; int vld = vld_s[r];
        const float* qrow = g_q + (size_t)d * H_;
        float s = 0.f;
#pragma unroll
        for (int j = 0; j < 16; j += 4) {
            float4 qv = *reinterpret_cast<const float4*>(qrow + hh * 16 + j);
            float4 kv = *reinterpret_cast<const float4*>(k_s + r * 128 + hh * 16 + j);
            s += qv.x * kv.x + qv.y * kv.y + qv.z * kv.z + qv.w * kv.w;
        }
        float ex = expf(s * 0.25f);
        ex_s[r * 8 + hh] = ex;
        if (vld) atomicAdd(&g_den[(size_t)d * 8 + hh], ex);
    }
    __syncthreads();

    {   // numerator scatter: 8 threads/edge, 16 cols each
        int r = tid >> 3, part = tid & 7;
        if (vld_s[r]) {
            int d = dst_s[r];
            float* xr = g_h + (size_t)d * H_;
            float exh0 = ex_s[r * 8 + part];
#pragma unroll
            for (int j = 0; j < 16; j++) {
                int c = part * 16 + j;
                atomicAdd(&xr[c], exh0 * v_s[r * 128 + c]);
            }
        }
    }
}

__global__ void STG_norm_kernel() {
    size_t i = (size_t)blockIdx.x * 256 + threadIdx.x;
    if (i >= (size_t)NE_ * H_) return;
    size_t n = i >> 7; int c = (int)(i & 127);
    float den = g_den[n * 8 + (c >> 4)];
    float x = g_h[i];
    g_h[i] = den > 0.f ? x / den : 0.f;
}

__global__ void STG_relcopy_kernel(const float* __restrict__ rel) {
    int i = blockIdx.x * 256 + threadIdx.x;
    if (i < NR_ * H_) g_h[(size_t)NE_ * H_ + i] = rel[i];
}

__global__ __launch_bounds__(256, 3) void STG_feval_kernel(
    int nk, float c1, float c2, float c3, float c4, float c5, int kout_idx,
    const float* __restrict__ spW1, const float* __restrict__ spb1,
    const float* __restrict__ spW2, const float* __restrict__ spb2,
    const float* __restrict__ tmW1, const float* __restrict__ tmb1,
    const float* __restrict__ tmW2, const float* __restrict__ tmb2,
    const float* __restrict__ fgW,  const float* __restrict__ fgb)
{
    extern __shared__ float sm[];
    float* h_s   = sm;               // 32*128 (reused as sp)
    float* a1_s  = sm + 32 * 128;    // 32*256 (reused as tm)
    float* a2_s  = a1_s + 32 * 256;  // 32*64
    float* sp_s  = h_s;
    float* tm2_s = a1_s;

    const int row0 = blockIdx.x * 32;
    for (int t = threadIdx.x; t < 32 * 32; t += 256) {
        int r = t >> 5, c = (t & 31) * 4; int g = row0 + r;
        float4 v = make_float4(0.f, 0.f, 0.f, 0.f);
        if (g < NROWS_) {
            size_t idx = (size_t)g * H_ + c;
            v = *reinterpret_cast<const float4*>(g_h + idx);
            float4 a;
            if (nk > 0) { a = *reinterpret_cast<const float4*>(g_k[0] + idx);
                v.x += c1 * a.x; v.y += c1 * a.y; v.z += c1 * a.z; v.w += c1 * a.w; }
            if (nk > 1) { a = *reinterpret_cast<const float4*>(g_k[1] + idx);
                v.x += c2 * a.x; v.y += c2 * a.y; v.z += c2 * a.z; v.w += c2 * a.w; }
            if (nk > 2) { a = *reinterpret_cast<const float4*>(g_k[2] + idx);
                v.x += c3 * a.x; v.y += c3 * a.y; v.z += c3 * a.z; v.w += c3 * a.w; }
            if (nk > 3) { a = *reinterpret_cast<const float4*>(g_k[3] + idx);
                v.x += c4 * a.x; v.y += c4 * a.y; v.z += c4 * a.z; v.w += c4 * a.w; }
            if (nk > 4) { a = *reinterpret_cast<const float4*>(g_k[4] + idx);
                v.x += c5 * a.x; v.y += c5 * a.y; v.z += c5 * a.z; v.w += c5 * a.w; }
        }
        *reinterpret_cast<float4*>(h_s + r * H_ + c) = v;
    }
    __syncthreads();

    gemmC<32, 256, 128>(h_s, 128, spW1, a1_s, 256,
        [&](int r, int c, float& x, float& y) { x = gelu_f(x + spb1[c]); y = gelu_f(y + spb1[c + 1]); });
    gemmC<32, 64, 128>(h_s, 128, tmW1, a2_s, 64,
        [&](int r, int c, float& x, float& y) { x = softplus_f(x + tmb1[c]); y = softplus_f(y + tmb1[c + 1]); });
    __syncthreads();

    gemmC<32, 128, 256>(a1_s, 256, spW2, sp_s, 128,
        [&](int r, int c, float& x, float& y) { x += spb2[c]; y += spb2[c + 1]; });
    __syncthreads();

    gemmC<32, 128, 64>(a2_s, 64, tmW2, tm2_s, 128,
        [&](int r, int c, float& x, float& y) { x += tmb2[c]; y += tmb2[c + 1]; });
    __syncthreads();

    {   // gate + output: 8 threads/row, 16 cols each
        int r = threadIdx.x >> 3, part = threadIdx.x & 7;
        float s0 = 0.f, s1 = 0.f;
#pragma unroll
        for (int jj = 0; jj < 16; jj++) {
            int d = part * 16 + jj;
            float spv = sp_s[r * 128 + d], tmv = tm2_s[r * 128 + d];
            s0 += spv * fgW[2 * d]     + tmv * fgW[2 * (128 + d)];
            s1 += spv * fgW[2 * d + 1] + tmv * fgW[2 * (128 + d) + 1];
        }
        s0 += __shfl_xor_sync(0xffffffffu, s0, 1);
        s1 += __shfl_xor_sync(0xffffffffu, s1, 1);
        s0 += __shfl_xor_sync(0xffffffffu, s0, 2);
        s1 += __shfl_xor_sync(0xffffffffu, s1, 2);
        s0 += __shfl_xor_sync(0xffffffffu, s0, 4);
        s1 += __shfl_xor_sync(0xffffffffu, s1, 4);
        float g0 = sigmoid_f(s0 + fgb[0]);
        float g1 = sigmoid_f(s1 + fgb[1]);
        int g = row0 + r;
        if (g < NROWS_) {
            float* ko = g_k[kout_idx] + (size_t)g * H_;
#pragma unroll
            for (int jj = 0; jj < 16; jj += 4) {
                int d = part * 16 + jj;
                float4 o;
                o.x = g0 * sp_s[r * 128 + d + 0] + g1 * tm2_s[r * 128 + d + 0];
                o.y = g0 * sp_s[r * 128 + d + 1] + g1 * tm2_s[r * 128 + d + 1];
                o.z = g0 * sp_s[r * 128 + d + 2] + g1 * tm2_s[r * 128 + d + 2];
                o.w = g0 * sp_s[r * 128 + d + 3] + g1 * tm2_s[r * 128 + d + 3];
                *reinterpret_cast<float4*>(ko + d) = o;
            }
        }
    }
}

__global__ void STG_combine_kernel(float b1, float b3, float b4, float b5, float b6) {
    size_t i = ((size_t)blockIdx.x * 256 + threadIdx.x) * 4;
    if (i >= (size_t)NROWS_ * H_) return;
    float4 h = *reinterpret_cast<const float4*>(g_h + i);
    float4 a = *reinterpret_cast<const float4*>(g_k[0] + i);
    float4 c = *reinterpret_cast<const float4*>(g_k[2] + i);
    float4 d = *reinterpret_cast<const float4*>(g_k[3] + i);
    float4 e = *reinterpret_cast<const float4*>(g_k[4] + i);
    float4 f = *reinterpret_cast<const float4*>(g_k[5] + i);
    h.x += b1 * a.x + b3 * c.x + b4 * d.x + b5 * e.x + b6 * f.x;
    h.y += b1 * a.y + b3 * c.y + b4 * d.y + b5 * e.y + b6 * f.y;
    h.z += b1 * a.z + b3 * c.z + b4 * d.z + b5 * e.z + b6 * f.z;
    h.w += b1 * a.w + b3 * c.w + b4 * d.w + b5 * e.w + b6 * f.w;
    *reinterpret_cast<float4*>(g_h + i) = h;
}

__global__ void STG_outcopy_kernel(float* __restrict__ out, int n4) {
    int i = blockIdx.x * 256 + threadIdx.x;
    if (i < n4)
        *reinterpret_cast<float4*>(out + (size_t)i * 4) =
            *reinterpret_cast<const float4*>(g_h + (size_t)i * 4);
}

extern "C" void kernel_launch(void* const* d_in, const int* in_sizes, int n_in,
                              void* d_out, int out_size)
{
    (void)in_sizes; (void)n_in;
    const float* ent  = (const float*)d_in[0];
    const float* rel  = (const float*)d_in[1];
    const float* drel = (const float*)d_in[2];
    const float* Wq   = (const float*)d_in[3];
    const float* bq   = (const float*)d_in[4];
    const float* Wk   = (const float*)d_in[5];
    const float* bk   = (const float*)d_in[6];
    const float* Wv   = (const float*)d_in[7];
    const float* bv   = (const float*)d_in[8];
    const float* tcoef= (const float*)d_in[9];
    const float* wgW1 = (const float*)d_in[10];
    const float* wgb1 = (const float*)d_in[11];
    const float* wgW2 = (const float*)d_in[12];
    const float* wgb2 = (const float*)d_in[13];
    const float* spW1 = (const float*)d_in[14];
    const float* spb1 = (const float*)d_in[15];
    const float* spW2 = (const float*)d_in[16];
    const float* spb2 = (const float*)d_in[17];
    const float* tmW1 = (const float*)d_in[18];
    const float* tmb1 = (const float*)d_in[19];
    const float* tmW2 = (const float*)d_in[20];
    const float* tmb2 = (const float*)d_in[21];
    const float* fgW  = (const float*)d_in[22];
    const float* fgb  = (const float*)d_in[23];
    const float* edge_time  = (const float*)d_in[24];
    const float* query_time = (const float*)d_in[25];
    const int* src  = (const int*)d_in[26];
    const int* dst  = (const int*)d_in[27];
    const int* etyp = (const int*)d_in[28];
    float* out = (float*)d_out;

    const int SM_QALL = 2 * 64 * 128 * 4;                                   // 65536
    const int SM_EDGE = (32*256 + 3*32*128 + 32 + 32 + 32*8 + 4*32) * 4;    // 83712
    const int SM_FEVL = (32*128 + 32*256 + 32*64) * 4;                      // 57344
    cudaFuncSetAttribute(STG_qall_kernel,  cudaFuncAttributeMaxDynamicSharedMemorySize, SM_QALL);
    cudaFuncSetAttribute(STG_edge_kernel,  cudaFuncAttributeMaxDynamicSharedMemorySize, SM_EDGE);
    cudaFuncSetAttribute(STG_feval_kernel, cudaFuncAttributeMaxDynamicSharedMemorySize, SM_FEVL);

    {
        size_t tot4 = ((size_t)NE_ * H_ + (size_t)NE_ * 8) / 4;
        int nb = (int)((tot4 + 255) / 256);
        STG_zero_kernel<<<nb, 256>>>();
    }
    STG_qall_kernel<<<(NE_ + 63) / 64, 256, SM_QALL>>>(ent, Wq, bq);
    STG_edge_kernel<<<(E_ + 31) / 32, 256, SM_EDGE>>>(
        ent, drel, Wk, bk, Wv, bv, wgW1, wgb1, wgW2, wgb2,
        tcoef, edge_time, query_time, src, dst, etyp);
    {
        size_t tot = (size_t)NE_ * H_;
        STG_norm_kernel<<<(int)((tot + 255) / 256), 256>>>();
    }
    STG_relcopy_kernel<<<(NR_ * H_ + 255) / 256, 256>>>(rel);

    const float dt = 1.0f / 8.0f;
    const int FB = (NROWS_ + 31) / 32;
    const int CB = (int)(((size_t)NROWS_ * H_ / 4 + 255) / 256);

    for (int s = 0; s < 8; s++) {
        STG_feval_kernel<<<FB, 256, SM_FEVL>>>(0, 0.f, 0.f, 0.f, 0.f, 0.f, 0,
            spW1, spb1, spW2, spb2, tmW1, tmb1, tmW2, tmb2, fgW, fgb);
        STG_feval_kernel<<<FB, 256, SM_FEVL>>>(1, dt * 0.2f, 0.f, 0.f, 0.f, 0.f, 1,
            spW1, spb1, spW2, spb2, tmW1, tmb1, tmW2, tmb2, fgW, fgb);
        STG_feval_kernel<<<FB, 256, SM_FEVL>>>(2,
            dt * (3.0f / 40.0f), dt * (9.0f / 40.0f), 0.f, 0.f, 0.f, 2,
            spW1, spb1, spW2, spb2, tmW1, tmb1, tmW2, tmb2, fgW, fgb);
        STG_feval_kernel<<<FB, 256, SM_FEVL>>>(3,
            dt * (44.0f / 45.0f), dt * (-56.0f / 15.0f), dt * (32.0f / 9.0f), 0.f, 0.f, 3,
            spW1, spb1, spW2, spb2, tmW1, tmb1, tmW2, tmb2, fgW, fgb);
        STG_feval_kernel<<<FB, 256, SM_FEVL>>>(4,
            dt * (19372.0f / 6561.0f), dt * (-25360.0f / 2187.0f),
            dt * (64448.0f / 6561.0f), dt * (-212.0f / 729.0f), 0.f, 4,
            spW1, spb1, spW2, spb2, tmW1, tmb1, tmW2, tmb2, fgW, fgb);
        STG_feval_kernel<<<FB, 256, SM_FEVL>>>(5,
            dt * (9017.0f / 3168.0f), dt * (-355.0f / 33.0f),
            dt * (46732.0f / 5247.0f), dt * (49.0f / 176.0f),
            dt * (-5103.0f / 18656.0f), 5,
            spW1, spb1, spW2, spb2, tmW1, tmb1, tmW2, tmb2, fgW, fgb);
        STG_combine_kernel<<<CB, 256>>>(
            dt * (35.0f / 384.0f), dt * (500.0f / 1113.0f), dt * (125.0f / 192.0f),
            dt * (-2187.0f / 6784.0f), dt * (11.0f / 84.0f));
    }

    {
        int n4 = out_size / 4;
        STG_outcopy_kernel<<<(n4 + 255) / 256, 256>>>(out, n4);
    }
}